// round 1
// baseline (speedup 1.0000x reference)
#include <cuda_runtime.h>
#include <cuda_bf16.h>

#define NN 8192
#define DD 256

// Scratch (device globals — no allocation allowed in kernel_launch)
__device__ float g_q[NN * DD];
__device__ float g_k[NN * DD];
__device__ float g_v[NN * DD];
__device__ float g_s[NN];
__device__ float g_alpha[NN];

// ---------------------------------------------------------------------------
// Kernel 1: q/k/v = x @ W + b   (BM=64, BN=64, BK=16, 256 threads, 4x4 micro)
// blockIdx.z selects which of the three projections.
// ---------------------------------------------------------------------------
__global__ __launch_bounds__(256) void qkv_kernel(
    const float* __restrict__ x,
    const float* __restrict__ Wq, const float* __restrict__ bq,
    const float* __restrict__ Wk, const float* __restrict__ bk,
    const float* __restrict__ Wv, const float* __restrict__ bv)
{
    const float* W;
    const float* b;
    float* out;
    if (blockIdx.z == 0)      { W = Wq; b = bq; out = g_q; }
    else if (blockIdx.z == 1) { W = Wk; b = bk; out = g_k; }
    else                      { W = Wv; b = bv; out = g_v; }

    __shared__ float As[16][68];   // x tile, transposed: As[kk][m] (+4 pad)
    __shared__ float Bs[16][64];   // W tile: Bs[kk][n]

    const int row0 = blockIdx.x * 64;
    const int col0 = blockIdx.y * 64;
    const int tid  = threadIdx.x;
    const int ty   = tid >> 4;     // 0..15 (row group)
    const int tx   = tid & 15;     // 0..15 (col group)

    float acc[4][4];
    #pragma unroll
    for (int r = 0; r < 4; r++)
        #pragma unroll
        for (int c = 0; c < 4; c++) acc[r][c] = 0.0f;

    for (int k0 = 0; k0 < DD; k0 += 16) {
        // load x tile (64x16), store transposed
        {
            int r  = tid >> 2;           // 0..63
            int k4 = (tid & 3) * 4;      // 0,4,8,12
            float4 v4 = *(const float4*)(x + (size_t)(row0 + r) * DD + k0 + k4);
            As[k4 + 0][r] = v4.x;
            As[k4 + 1][r] = v4.y;
            As[k4 + 2][r] = v4.z;
            As[k4 + 3][r] = v4.w;
        }
        // load W tile (16x64)
        {
            int kk = tid >> 4;           // 0..15
            int c4 = (tid & 15) * 4;     // 0..60
            float4 v4 = *(const float4*)(W + (size_t)(k0 + kk) * DD + col0 + c4);
            *(float4*)&Bs[kk][c4] = v4;
        }
        __syncthreads();

        #pragma unroll
        for (int kk = 0; kk < 16; kk++) {
            float4 a4 = *(const float4*)&As[kk][ty * 4];
            float4 b4 = *(const float4*)&Bs[kk][tx * 4];
            float a[4] = {a4.x, a4.y, a4.z, a4.w};
            float bb[4] = {b4.x, b4.y, b4.z, b4.w};
            #pragma unroll
            for (int r = 0; r < 4; r++)
                #pragma unroll
                for (int c = 0; c < 4; c++)
                    acc[r][c] += a[r] * bb[c];
        }
        __syncthreads();
    }

    #pragma unroll
    for (int r = 0; r < 4; r++) {
        int row = row0 + ty * 4 + r;
        #pragma unroll
        for (int c = 0; c < 4; c++) {
            int col = col0 + tx * 4 + c;
            out[(size_t)row * DD + col] = acc[r][c] + b[col];
        }
    }
}

// ---------------------------------------------------------------------------
// Kernel 2: s[i] = q[i] . (adj @ k)[i]
// Block computes BM=64 rows x full D=256 cols of m = adj@k (fp32 accum),
// then fuses the dot with q and a warp reduction. 256 threads = 8 warps;
// warp w owns row group w (8 rows), lane owns col groups {cr*4, cr*4+128}.
// ---------------------------------------------------------------------------
__global__ __launch_bounds__(256) void s_kernel(const float* __restrict__ adj)
{
    __shared__ float As[16][68];    // adj tile transposed: As[kk][row] (+4 pad)
    __shared__ float Ks[16][256];   // k tile: Ks[kk][col]

    const int row0 = blockIdx.x * 64;
    const int tid  = threadIdx.x;
    const int rr   = tid >> 5;      // warp id = row group (0..7)
    const int cr   = tid & 31;      // lane = col group (0..31)
    const int c0   = cr * 4;

    float acc[8][8];
    #pragma unroll
    for (int r = 0; r < 8; r++)
        #pragma unroll
        for (int c = 0; c < 8; c++) acc[r][c] = 0.0f;

    for (int j0 = 0; j0 < NN; j0 += 16) {
        // adj tile 64x16 -> transposed smem
        {
            int r  = tid >> 2;
            int k4 = (tid & 3) * 4;
            float4 v4 = *(const float4*)(adj + (size_t)(row0 + r) * NN + j0 + k4);
            As[k4 + 0][r] = v4.x;
            As[k4 + 1][r] = v4.y;
            As[k4 + 2][r] = v4.z;
            As[k4 + 3][r] = v4.w;
        }
        // k tile 16x256 (4 float4 per thread)
        #pragma unroll
        for (int u = 0; u < 4; u++) {
            int idx = tid + u * 256;       // 0..1023
            int kk  = idx >> 6;
            int c4  = (idx & 63) * 4;
            float4 v4 = *(const float4*)(g_k + (size_t)(j0 + kk) * DD + c4);
            *(float4*)&Ks[kk][c4] = v4;
        }
        __syncthreads();

        #pragma unroll
        for (int kk = 0; kk < 16; kk++) {
            float4 a0 = *(const float4*)&As[kk][rr * 8];
            float4 a1 = *(const float4*)&As[kk][rr * 8 + 4];
            float4 b0 = *(const float4*)&Ks[kk][c0];
            float4 b1 = *(const float4*)&Ks[kk][c0 + 128];
            float a[8] = {a0.x, a0.y, a0.z, a0.w, a1.x, a1.y, a1.z, a1.w};
            float bb[8] = {b0.x, b0.y, b0.z, b0.w, b1.x, b1.y, b1.z, b1.w};
            #pragma unroll
            for (int r = 0; r < 8; r++)
                #pragma unroll
                for (int c = 0; c < 8; c++)
                    acc[r][c] += a[r] * bb[c];
        }
        __syncthreads();
    }

    // fuse: p[r] = sum_c m[row][col_c] * q[row][col_c], warp-reduce over lanes
    #pragma unroll
    for (int r = 0; r < 8; r++) {
        int row = row0 + rr * 8 + r;
        const float* qrow = g_q + (size_t)row * DD;
        float4 q0 = *(const float4*)(qrow + c0);
        float4 q1 = *(const float4*)(qrow + c0 + 128);
        float p = acc[r][0] * q0.x + acc[r][1] * q0.y + acc[r][2] * q0.z + acc[r][3] * q0.w
                + acc[r][4] * q1.x + acc[r][5] * q1.y + acc[r][6] * q1.z + acc[r][7] * q1.w;
        #pragma unroll
        for (int off = 16; off > 0; off >>= 1)
            p += __shfl_down_sync(0xffffffffu, p, off);
        if (cr == 0) g_s[row] = p;
    }
}

// ---------------------------------------------------------------------------
// Kernel 3: alpha = softmax(s)  (single block, 1024 threads, 8 elems each)
// ---------------------------------------------------------------------------
__global__ __launch_bounds__(1024) void softmax_kernel(float* __restrict__ alpha_out,
                                                       int write_tail)
{
    __shared__ float red[32];
    const int tid = threadIdx.x;
    const int lane = tid & 31;
    const int wid = tid >> 5;

    // pass 1: max
    float lmax = -3.4e38f;
    for (int i = tid; i < NN; i += 1024) lmax = fmaxf(lmax, g_s[i]);
    #pragma unroll
    for (int off = 16; off > 0; off >>= 1)
        lmax = fmaxf(lmax, __shfl_xor_sync(0xffffffffu, lmax, off));
    if (lane == 0) red[wid] = lmax;
    __syncthreads();
    float bmax = red[lane & 31];
    if (lane >= 32) bmax = -3.4e38f;
    // reduce 32 warp maxima (in every warp, cheap)
    float m = red[lane];
    #pragma unroll
    for (int off = 16; off > 0; off >>= 1)
        m = fmaxf(m, __shfl_xor_sync(0xffffffffu, m, off));
    (void)bmax;
    __syncthreads();

    // pass 2: exp + sum
    float lsum = 0.0f;
    for (int i = tid; i < NN; i += 1024) {
        float e = expf(g_s[i] - m);
        g_alpha[i] = e;
        lsum += e;
    }
    #pragma unroll
    for (int off = 16; off > 0; off >>= 1)
        lsum += __shfl_xor_sync(0xffffffffu, lsum, off);
    if (lane == 0) red[wid] = lsum;
    __syncthreads();
    float ssum = red[lane];
    #pragma unroll
    for (int off = 16; off > 0; off >>= 1)
        ssum += __shfl_xor_sync(0xffffffffu, ssum, off);
    float inv = 1.0f / ssum;

    // pass 3: normalize + optionally write alpha tail of d_out
    for (int i = tid; i < NN; i += 1024) {
        float a = g_alpha[i] * inv;
        g_alpha[i] = a;
        if (write_tail) alpha_out[i] = a;
    }
}

// ---------------------------------------------------------------------------
// Kernel 4: out[i, :] = alpha[i] * v[i, :]   (float4 vectorized)
// ---------------------------------------------------------------------------
__global__ __launch_bounds__(256) void out_kernel(float* __restrict__ out)
{
    int idx = blockIdx.x * blockDim.x + threadIdx.x;   // float4 index
    const int total4 = NN * DD / 4;
    if (idx >= total4) return;
    int row = (idx * 4) / DD;
    float a = g_alpha[row];
    float4 v4 = *(const float4*)(g_v + (size_t)idx * 4);
    v4.x *= a; v4.y *= a; v4.z *= a; v4.w *= a;
    *(float4*)(out + (size_t)idx * 4) = v4;
}

// ---------------------------------------------------------------------------
extern "C" void kernel_launch(void* const* d_in, const int* in_sizes, int n_in,
                              void* d_out, int out_size) {
    const float* x   = (const float*)d_in[0];
    const float* adj = (const float*)d_in[1];
    const float* Wq  = (const float*)d_in[2];
    const float* bq  = (const float*)d_in[3];
    const float* Wk  = (const float*)d_in[4];
    const float* bk  = (const float*)d_in[5];
    const float* Wv  = (const float*)d_in[6];
    const float* bv  = (const float*)d_in[7];
    float* out = (float*)d_out;

    // 1) q, k, v projections
    dim3 g1(NN / 64, DD / 64, 3);
    qkv_kernel<<<g1, 256>>>(x, Wq, bq, Wk, bk, Wv, bv);

    // 2) s = rowdot(q, adj @ k)
    s_kernel<<<NN / 64, 256>>>(adj);

    // 3) alpha = softmax(s); write alpha tail if output has room for it
    int write_tail = (out_size >= NN * DD + NN) ? 1 : 0;
    softmax_kernel<<<1, 1024>>>(out + (size_t)NN * DD, write_tail);

    // 4) out = alpha[:,None] * v
    int total4 = NN * DD / 4;
    out_kernel<<<(total4 + 255) / 256, 256>>>(out);
}

// round 6
// speedup vs baseline: 2.9953x; 2.9953x over previous
#include <cuda_runtime.h>
#include <cuda_fp16.h>
#include <cuda_bf16.h>
#include <cstdint>

#define NN 8192
#define DD 256

// ---------------- scratch (device globals; no allocation allowed) ----------
__device__ float  g_q[NN * DD];
__device__ float  g_k[NN * DD];
__device__ float  g_v[NN * DD];
__device__ __half g_adj_h[(size_t)NN * NN];   // adj in fp16 (exact: 0/1)
__device__ __half g_kh[NN * DD];              // k hi split  [j][d]
__device__ __half g_kl[NN * DD];              // k lo split  [j][d]
__device__ float  g_spart[2 * NN];            // per-N-tile partials (deterministic)
__device__ float  g_s[NN];
__device__ float  g_alpha[NN];

// ---------------- PTX helpers (base sm_80+ ISA only; NO 103a features) -----
__device__ __forceinline__ uint32_t cvta_smem(const void* p) {
    uint32_t a;
    asm("{ .reg .u64 t; cvta.to.shared.u64 t, %1; cvt.u32.u64 %0, t; }"
        : "=r"(a) : "l"(p));
    return a;
}

__device__ __forceinline__ void cp16(uint32_t dst, const void* src) {
    asm volatile("cp.async.cg.shared.global [%0], [%1], 16;" :: "r"(dst), "l"(src));
}
__device__ __forceinline__ void cp_commit() {
    asm volatile("cp.async.commit_group;" ::: "memory");
}
template <int N>
__device__ __forceinline__ void cp_wait() {
    asm volatile("cp.async.wait_group %0;" :: "n"(N) : "memory");
}

__device__ __forceinline__ void ldm_x4(uint32_t addr, uint32_t& r0, uint32_t& r1,
                                       uint32_t& r2, uint32_t& r3) {
    asm volatile("ldmatrix.sync.aligned.m8n8.x4.shared.b16 {%0,%1,%2,%3}, [%4];"
                 : "=r"(r0), "=r"(r1), "=r"(r2), "=r"(r3) : "r"(addr));
}
__device__ __forceinline__ void ldm_x4_t(uint32_t addr, uint32_t& r0, uint32_t& r1,
                                         uint32_t& r2, uint32_t& r3) {
    asm volatile("ldmatrix.sync.aligned.m8n8.x4.trans.shared.b16 {%0,%1,%2,%3}, [%4];"
                 : "=r"(r0), "=r"(r1), "=r"(r2), "=r"(r3) : "r"(addr));
}

__device__ __forceinline__ void mma16816(float* c, uint32_t a0, uint32_t a1,
                                         uint32_t a2, uint32_t a3,
                                         uint32_t b0, uint32_t b1) {
    asm volatile(
        "mma.sync.aligned.m16n8k16.row.col.f32.f16.f16.f32 "
        "{%0,%1,%2,%3}, {%4,%5,%6,%7}, {%8,%9}, {%0,%1,%2,%3};"
        : "+f"(c[0]), "+f"(c[1]), "+f"(c[2]), "+f"(c[3])
        : "r"(a0), "r"(a1), "r"(a2), "r"(a3), "r"(b0), "r"(b1));
}

// ---------------------------------------------------------------------------
// Kernel 1: q/k/v = x @ W + b   (round-1 SIMT version, known passing)
// ---------------------------------------------------------------------------
__global__ __launch_bounds__(256) void qkv_kernel(
    const float* __restrict__ x,
    const float* __restrict__ Wq, const float* __restrict__ bq,
    const float* __restrict__ Wk, const float* __restrict__ bk,
    const float* __restrict__ Wv, const float* __restrict__ bv)
{
    const float* W;
    const float* b;
    float* out;
    if (blockIdx.z == 0)      { W = Wq; b = bq; out = g_q; }
    else if (blockIdx.z == 1) { W = Wk; b = bk; out = g_k; }
    else                      { W = Wv; b = bv; out = g_v; }

    __shared__ float As[16][68];
    __shared__ float Bs[16][64];

    const int row0 = blockIdx.x * 64;
    const int col0 = blockIdx.y * 64;
    const int tid  = threadIdx.x;
    const int ty   = tid >> 4;
    const int tx   = tid & 15;

    float acc[4][4];
    #pragma unroll
    for (int r = 0; r < 4; r++)
        #pragma unroll
        for (int c = 0; c < 4; c++) acc[r][c] = 0.0f;

    for (int k0 = 0; k0 < DD; k0 += 16) {
        {
            int r  = tid >> 2;
            int k4 = (tid & 3) * 4;
            float4 v4 = *(const float4*)(x + (size_t)(row0 + r) * DD + k0 + k4);
            As[k4 + 0][r] = v4.x;
            As[k4 + 1][r] = v4.y;
            As[k4 + 2][r] = v4.z;
            As[k4 + 3][r] = v4.w;
        }
        {
            int kk = tid >> 4;
            int c4 = (tid & 15) * 4;
            float4 v4 = *(const float4*)(W + (size_t)(k0 + kk) * DD + col0 + c4);
            *(float4*)&Bs[kk][c4] = v4;
        }
        __syncthreads();

        #pragma unroll
        for (int kk = 0; kk < 16; kk++) {
            float4 a4 = *(const float4*)&As[kk][ty * 4];
            float4 b4 = *(const float4*)&Bs[kk][tx * 4];
            float a[4] = {a4.x, a4.y, a4.z, a4.w};
            float bb[4] = {b4.x, b4.y, b4.z, b4.w};
            #pragma unroll
            for (int r = 0; r < 4; r++)
                #pragma unroll
                for (int c = 0; c < 4; c++)
                    acc[r][c] += a[r] * bb[c];
        }
        __syncthreads();
    }

    #pragma unroll
    for (int r = 0; r < 4; r++) {
        int row = row0 + ty * 4 + r;
        #pragma unroll
        for (int c = 0; c < 4; c++) {
            int col = col0 + tx * 4 + c;
            out[(size_t)row * DD + col] = acc[r][c] + b[col];
        }
    }
}

// ---------------------------------------------------------------------------
// Kernel 2a: adj (fp32) -> fp16 (values are 0/1: exact)
// ---------------------------------------------------------------------------
__global__ __launch_bounds__(256) void adj2h_kernel(const float* __restrict__ adj)
{
    size_t i4 = (size_t)blockIdx.x * blockDim.x + threadIdx.x;   // float4 index
    const size_t total4 = (size_t)NN * NN / 4;
    if (i4 >= total4) return;
    float4 a = *(const float4*)(adj + i4 * 4);
    __half2 h0 = __floats2half2_rn(a.x, a.y);
    __half2 h1 = __floats2half2_rn(a.z, a.w);
    *(__half2*)(g_adj_h + i4 * 4)     = h0;
    *(__half2*)(g_adj_h + i4 * 4 + 2) = h1;
}

// ---------------------------------------------------------------------------
// Kernel 2b: k -> fp16 hi/lo split (hi + lo carries ~22 mantissa bits)
// ---------------------------------------------------------------------------
__global__ __launch_bounds__(256) void ksplit_kernel()
{
    size_t i4 = (size_t)blockIdx.x * blockDim.x + threadIdx.x;
    const size_t total4 = (size_t)NN * DD / 4;
    if (i4 >= total4) return;
    float4 kv = *(const float4*)(g_k + i4 * 4);
    float vs[4] = {kv.x, kv.y, kv.z, kv.w};
    __half hi[4], lo[4];
    #pragma unroll
    for (int i = 0; i < 4; i++) {
        hi[i] = __float2half_rn(vs[i]);
        lo[i] = __float2half_rn(vs[i] - __half2float(hi[i]));
    }
    *(__half2*)(g_kh + i4 * 4)     = __halves2half2(hi[0], hi[1]);
    *(__half2*)(g_kh + i4 * 4 + 2) = __halves2half2(hi[2], hi[3]);
    *(__half2*)(g_kl + i4 * 4)     = __halves2half2(lo[0], lo[1]);
    *(__half2*)(g_kl + i4 * 4 + 2) = __halves2half2(lo[2], lo[3]);
}

// ---------------------------------------------------------------------------
// Kernel 3: s_part = rowdot(adj @ (k_hi + k_lo), q) via mma.sync fp16 (f32 acc)
// Grid (NN/128, 2). CTA tile M=128 x N=128, K-chunk 64, 3-stage cp.async ring.
// 8 warps: warp_m = wid>>1 (32 rows each), warp_n = wid&1 (64 cols each).
// ---------------------------------------------------------------------------
#define SG_ITERS   (NN / 64)
#define LDA_H      72                       // 64 + 8 pad (halfs)
#define LDB_H      136                      // 128 + 8 pad (halfs)
#define A_BYTES    (128 * LDA_H * 2)        // 18432
#define B_BYTES    (64 * LDB_H * 2)         // 17408
#define STAGE_B    (A_BYTES + 2 * B_BYTES)  // 53248
#define NSTAGE     3

__global__ __launch_bounds__(256, 1) void smma_kernel()
{
    extern __shared__ char smem[];
    __shared__ float srow[2][128];

    const int tid  = threadIdx.x;
    const int wid  = tid >> 5;
    const int lane = tid & 31;
    const int warp_m = wid >> 1;      // 0..3
    const int warp_n = wid & 1;       // 0..1
    const int row0 = blockIdx.x * 128;
    const int n0   = blockIdx.y * 128;
    const uint32_t sbase = cvta_smem(smem);

    float acc[2][8][4];
    #pragma unroll
    for (int m = 0; m < 2; m++)
        #pragma unroll
        for (int n = 0; n < 8; n++)
            #pragma unroll
            for (int i = 0; i < 4; i++) acc[m][n][i] = 0.0f;

    // ---- loader lambda-ish (macro): fill stage `st` with K-chunk `it` ----
    #define LOAD_STAGE(st, it)                                                   \
    do {                                                                         \
        const int j0 = (it) * 64;                                                \
        const uint32_t sa = sbase + (st) * STAGE_B;                              \
        const uint32_t sh = sa + A_BYTES;                                        \
        const uint32_t sl = sh + B_BYTES;                                        \
        _Pragma("unroll")                                                        \
        for (int u = 0; u < 4; u++) {                                            \
            int c = tid + u * 256;             /* 0..1023 */                     \
            int r  = c >> 3;                    /* 0..127 */                     \
            int k8 = (c & 7) * 8;                                                \
            cp16(sa + (uint32_t)(r * LDA_H + k8) * 2,                            \
                 g_adj_h + (size_t)(row0 + r) * NN + j0 + k8);                   \
        }                                                                        \
        _Pragma("unroll")                                                        \
        for (int u = 0; u < 4; u++) {                                            \
            int c = tid + u * 256;                                               \
            int r  = c >> 4;                    /* 0..63 */                      \
            int n8 = (c & 15) * 8;                                               \
            cp16(sh + (uint32_t)(r * LDB_H + n8) * 2,                            \
                 g_kh + (size_t)(j0 + r) * DD + n0 + n8);                        \
            cp16(sl + (uint32_t)(r * LDB_H + n8) * 2,                            \
                 g_kl + (size_t)(j0 + r) * DD + n0 + n8);                        \
        }                                                                        \
    } while (0)

    // preload
    #pragma unroll
    for (int p = 0; p < NSTAGE; p++) {
        LOAD_STAGE(p, p);
        cp_commit();
    }

    int buf = 0;
    for (int it = 0; it < SG_ITERS; ++it) {
        cp_wait<2>();
        __syncthreads();

        const uint32_t sa = sbase + buf * STAGE_B;
        const uint32_t sh = sa + A_BYTES;
        const uint32_t sl = sh + B_BYTES;

        #pragma unroll
        for (int kk = 0; kk < 4; kk++) {      // 4 k-steps of 16
            // A fragments (adj): 2 m-frags of 16x16
            uint32_t a[2][4];
            #pragma unroll
            for (int mf = 0; mf < 2; mf++) {
                int arow = warp_m * 32 + mf * 16 + (lane & 15);
                int acol = kk * 16 + (lane >> 4) * 8;
                ldm_x4(sa + (uint32_t)(arow * LDA_H + acol) * 2,
                       a[mf][0], a[mf][1], a[mf][2], a[mf][3]);
            }
            // B fragments: 8 n-frags per split (4 ldmatrix.x4.trans each)
            uint32_t bh[8][2], bl[8][2];
            #pragma unroll
            for (int nq = 0; nq < 4; nq++) {  // 16-col groups
                int brow = kk * 16 + (lane & 15);
                int bcol = warp_n * 64 + nq * 16 + (lane >> 4) * 8;
                uint32_t off = (uint32_t)(brow * LDB_H + bcol) * 2;
                ldm_x4_t(sh + off, bh[nq*2][0], bh[nq*2][1], bh[nq*2+1][0], bh[nq*2+1][1]);
                ldm_x4_t(sl + off, bl[nq*2][0], bl[nq*2][1], bl[nq*2+1][0], bl[nq*2+1][1]);
            }
            #pragma unroll
            for (int mf = 0; mf < 2; mf++)
                #pragma unroll
                for (int nf = 0; nf < 8; nf++) {
                    mma16816(acc[mf][nf], a[mf][0], a[mf][1], a[mf][2], a[mf][3],
                             bh[nf][0], bh[nf][1]);
                    mma16816(acc[mf][nf], a[mf][0], a[mf][1], a[mf][2], a[mf][3],
                             bl[nf][0], bl[nf][1]);
                }
        }
        __syncthreads();

        if (it + NSTAGE < SG_ITERS) LOAD_STAGE(buf, it + NSTAGE);
        cp_commit();
        if (++buf == NSTAGE) buf = 0;
    }

    // ---- fused epilogue: p[row] = sum_n m[row][n] * q[row][n0+n] ----------
    #pragma unroll
    for (int mf = 0; mf < 2; mf++) {
        #pragma unroll
        for (int rr = 0; rr < 2; rr++) {
            int lrow = warp_m * 32 + mf * 16 + rr * 8 + (lane >> 2);
            int grow = row0 + lrow;
            float p = 0.0f;
            #pragma unroll
            for (int nf = 0; nf < 8; nf++) {
                int gcol = n0 + warp_n * 64 + nf * 8 + (lane & 3) * 2;
                float2 qq = *(const float2*)(g_q + (size_t)grow * DD + gcol);
                p += acc[mf][nf][rr * 2 + 0] * qq.x
                   + acc[mf][nf][rr * 2 + 1] * qq.y;
            }
            p += __shfl_xor_sync(0xffffffffu, p, 1);
            p += __shfl_xor_sync(0xffffffffu, p, 2);
            if ((lane & 3) == 0) srow[warp_n][lrow] = p;
        }
    }
    __syncthreads();
    if (tid < 128)
        g_spart[(size_t)blockIdx.y * NN + row0 + tid] = srow[0][tid] + srow[1][tid];
}

// ---------------------------------------------------------------------------
// Kernel 4: alpha = softmax(s),  s = spart0 + spart1
// ---------------------------------------------------------------------------
__global__ __launch_bounds__(1024) void softmax_kernel(float* __restrict__ alpha_out,
                                                       int write_tail)
{
    __shared__ float red[32];
    const int tid = threadIdx.x;
    const int lane = tid & 31;
    const int wid = tid >> 5;

    float lmax = -3.4e38f;
    for (int i = tid; i < NN; i += 1024) {
        float sv = g_spart[i] + g_spart[NN + i];
        g_s[i] = sv;
        lmax = fmaxf(lmax, sv);
    }
    #pragma unroll
    for (int off = 16; off > 0; off >>= 1)
        lmax = fmaxf(lmax, __shfl_xor_sync(0xffffffffu, lmax, off));
    if (lane == 0) red[wid] = lmax;
    __syncthreads();
    float m = red[lane];
    #pragma unroll
    for (int off = 16; off > 0; off >>= 1)
        m = fmaxf(m, __shfl_xor_sync(0xffffffffu, m, off));
    __syncthreads();

    float lsum = 0.0f;
    for (int i = tid; i < NN; i += 1024) {
        float e = expf(g_s[i] - m);
        g_alpha[i] = e;
        lsum += e;
    }
    #pragma unroll
    for (int off = 16; off > 0; off >>= 1)
        lsum += __shfl_xor_sync(0xffffffffu, lsum, off);
    if (lane == 0) red[wid] = lsum;
    __syncthreads();
    float ssum = red[lane];
    #pragma unroll
    for (int off = 16; off > 0; off >>= 1)
        ssum += __shfl_xor_sync(0xffffffffu, ssum, off);
    float inv = 1.0f / ssum;

    for (int i = tid; i < NN; i += 1024) {
        float a = g_alpha[i] * inv;
        g_alpha[i] = a;
        if (write_tail) alpha_out[i] = a;
    }
}

// ---------------------------------------------------------------------------
// Kernel 5: out[i, :] = alpha[i] * v[i, :]
// ---------------------------------------------------------------------------
__global__ __launch_bounds__(256) void out_kernel(float* __restrict__ out)
{
    int idx = blockIdx.x * blockDim.x + threadIdx.x;
    const int total4 = NN * DD / 4;
    if (idx >= total4) return;
    int row = (idx * 4) / DD;
    float a = g_alpha[row];
    float4 v4 = *(const float4*)(g_v + (size_t)idx * 4);
    v4.x *= a; v4.y *= a; v4.z *= a; v4.w *= a;
    *(float4*)(out + (size_t)idx * 4) = v4;
}

// ---------------------------------------------------------------------------
extern "C" void kernel_launch(void* const* d_in, const int* in_sizes, int n_in,
                              void* d_out, int out_size) {
    const float* x   = (const float*)d_in[0];
    const float* adj = (const float*)d_in[1];
    const float* Wq  = (const float*)d_in[2];
    const float* bq  = (const float*)d_in[3];
    const float* Wk  = (const float*)d_in[4];
    const float* bk  = (const float*)d_in[5];
    const float* Wv  = (const float*)d_in[6];
    const float* bv  = (const float*)d_in[7];
    float* out = (float*)d_out;

    // adj -> fp16 (independent of qkv; issue first)
    {
        size_t total4 = (size_t)NN * NN / 4;
        adj2h_kernel<<<(unsigned)((total4 + 255) / 256), 256>>>(adj);
    }

    // q, k, v projections
    dim3 g1(NN / 64, DD / 64, 3);
    qkv_kernel<<<g1, 256>>>(x, Wq, bq, Wk, bk, Wv, bv);

    // k -> fp16 hi/lo
    {
        size_t total4 = (size_t)NN * DD / 4;
        ksplit_kernel<<<(unsigned)((total4 + 255) / 256), 256>>>();
    }

    // s partials via fp16 mma.sync GEMM + fused rowdot epilogue
    cudaFuncSetAttribute(smma_kernel, cudaFuncAttributeMaxDynamicSharedMemorySize,
                         NSTAGE * STAGE_B);
    dim3 g3(NN / 128, 2);
    smma_kernel<<<g3, 256, NSTAGE * STAGE_B>>>();

    // softmax
    int write_tail = (out_size >= NN * DD + NN) ? 1 : 0;
    softmax_kernel<<<1, 1024>>>(out + (size_t)NN * DD, write_tail);

    // out = alpha[:,None] * v
    int total4 = NN * DD / 4;
    out_kernel<<<(total4 + 255) / 256, 256>>>(out);
}

// round 7
// speedup vs baseline: 3.6072x; 1.2043x over previous
#include <cuda_runtime.h>
#include <cuda_fp16.h>
#include <cstdint>

#define NN 8192
#define DD 256

// ---------------- scratch (device globals; no allocation allowed) ----------
__device__ float  g_q[NN * DD];
__device__ float  g_v[NN * DD];
__device__ __half g_adj_h[(size_t)NN * NN];   // adj in fp16 (exact: 0/1)
__device__ __half g_xh[NN * DD];              // x hi split
__device__ __half g_xl[NN * DD];              // x lo split
__device__ __half g_wh[3 * DD * DD];          // Wq|Wk|Wv hi split
__device__ __half g_wl[3 * DD * DD];          // Wq|Wk|Wv lo split
__device__ __half g_kh[NN * DD];              // k hi split [j][d]
__device__ __half g_kl[NN * DD];              // k lo split
__device__ float  g_spart[4 * NN];            // deterministic partials
__device__ float  g_s[NN];
__device__ float  g_alpha[NN];

// ---------------- PTX helpers (base sm_80+ ISA only) ------------------------
__device__ __forceinline__ uint32_t cvta_smem(const void* p) {
    uint32_t a;
    asm("{ .reg .u64 t; cvta.to.shared.u64 t, %1; cvt.u32.u64 %0, t; }"
        : "=r"(a) : "l"(p));
    return a;
}
__device__ __forceinline__ void cp16(uint32_t dst, const void* src) {
    asm volatile("cp.async.cg.shared.global [%0], [%1], 16;" :: "r"(dst), "l"(src));
}
__device__ __forceinline__ void cp_commit() {
    asm volatile("cp.async.commit_group;" ::: "memory");
}
template <int N>
__device__ __forceinline__ void cp_wait() {
    asm volatile("cp.async.wait_group %0;" :: "n"(N) : "memory");
}
__device__ __forceinline__ void ldm_x4(uint32_t addr, uint32_t& r0, uint32_t& r1,
                                       uint32_t& r2, uint32_t& r3) {
    asm volatile("ldmatrix.sync.aligned.m8n8.x4.shared.b16 {%0,%1,%2,%3}, [%4];"
                 : "=r"(r0), "=r"(r1), "=r"(r2), "=r"(r3) : "r"(addr));
}
__device__ __forceinline__ void ldm_x4_t(uint32_t addr, uint32_t& r0, uint32_t& r1,
                                         uint32_t& r2, uint32_t& r3) {
    asm volatile("ldmatrix.sync.aligned.m8n8.x4.trans.shared.b16 {%0,%1,%2,%3}, [%4];"
                 : "=r"(r0), "=r"(r1), "=r"(r2), "=r"(r3) : "r"(addr));
}
__device__ __forceinline__ void mma16816(float* c, const uint32_t* a,
                                         uint32_t b0, uint32_t b1) {
    asm volatile(
        "mma.sync.aligned.m16n8k16.row.col.f32.f16.f16.f32 "
        "{%0,%1,%2,%3}, {%4,%5,%6,%7}, {%8,%9}, {%0,%1,%2,%3};"
        : "+f"(c[0]), "+f"(c[1]), "+f"(c[2]), "+f"(c[3])
        : "r"(a[0]), "r"(a[1]), "r"(a[2]), "r"(a[3]), "r"(b0), "r"(b1));
}

// ---------------------------------------------------------------------------
// Converters
// ---------------------------------------------------------------------------
__global__ __launch_bounds__(256) void adj2h_kernel(const float* __restrict__ adj)
{
    size_t i4 = (size_t)blockIdx.x * blockDim.x + threadIdx.x;
    const size_t total4 = (size_t)NN * NN / 4;
    if (i4 >= total4) return;
    float4 a = *(const float4*)(adj + i4 * 4);
    *(__half2*)(g_adj_h + i4 * 4)     = __floats2half2_rn(a.x, a.y);
    *(__half2*)(g_adj_h + i4 * 4 + 2) = __floats2half2_rn(a.z, a.w);
}

__global__ __launch_bounds__(256) void xsplit_kernel(const float* __restrict__ x)
{
    size_t i4 = (size_t)blockIdx.x * blockDim.x + threadIdx.x;
    const size_t total4 = (size_t)NN * DD / 4;
    if (i4 >= total4) return;
    float4 xv = *(const float4*)(x + i4 * 4);
    float vs[4] = {xv.x, xv.y, xv.z, xv.w};
    __half hi[4], lo[4];
    #pragma unroll
    for (int i = 0; i < 4; i++) {
        hi[i] = __float2half_rn(vs[i]);
        lo[i] = __float2half_rn(vs[i] - __half2float(hi[i]));
    }
    *(__half2*)(g_xh + i4 * 4)     = __halves2half2(hi[0], hi[1]);
    *(__half2*)(g_xh + i4 * 4 + 2) = __halves2half2(hi[2], hi[3]);
    *(__half2*)(g_xl + i4 * 4)     = __halves2half2(lo[0], lo[1]);
    *(__half2*)(g_xl + i4 * 4 + 2) = __halves2half2(lo[2], lo[3]);
}

__global__ __launch_bounds__(256) void wsplit_kernel(const float* __restrict__ Wq,
                                                     const float* __restrict__ Wk,
                                                     const float* __restrict__ Wv)
{
    int idx = blockIdx.x * blockDim.x + threadIdx.x;  // 0 .. 3*65536-1
    if (idx >= 3 * DD * DD) return;
    int z = idx / (DD * DD);
    int r = idx - z * (DD * DD);
    const float* W = (z == 0) ? Wq : (z == 1) ? Wk : Wv;
    float v = W[r];
    __half hi = __float2half_rn(v);
    __half lo = __float2half_rn(v - __half2float(hi));
    g_wh[idx] = hi;
    g_wl[idx] = lo;
}

// ---------------------------------------------------------------------------
// Kernel: q/k/v = x @ W + b via mma.sync, x and W fp16 hi/lo split (3 products)
// grid (64 Mtiles, 2 Ntiles, 3 matrices); 256 threads; tile 128x128, KC=64.
// z==1 (k) epilogue writes g_kh/g_kl directly.
// ---------------------------------------------------------------------------
#define Q_ITERS   (DD / 64)                 // 4
#define QLDA      72
#define QLDB      136
#define QA_B      (128 * QLDA * 2)          // 18432 (per split)
#define QB_B      (64 * QLDB * 2)           // 17408 (per split)
#define QSTAGE_B  (2 * QA_B + 2 * QB_B)     // 71680
#define QNSTAGE   2

__global__ __launch_bounds__(256, 1) void qkvmma_kernel(
    const float* __restrict__ bq, const float* __restrict__ bk,
    const float* __restrict__ bv)
{
    extern __shared__ char smem[];
    const int tid  = threadIdx.x;
    const int wid  = tid >> 5;
    const int lane = tid & 31;
    const int warp_m = wid >> 1;
    const int warp_n = wid & 1;
    const int row0 = blockIdx.x * 128;
    const int n0   = blockIdx.y * 128;
    const int z    = blockIdx.z;
    const __half* Wh = g_wh + (size_t)z * DD * DD;
    const __half* Wl = g_wl + (size_t)z * DD * DD;
    const uint32_t sbase = cvta_smem(smem);

    float acc[2][8][4];
    #pragma unroll
    for (int m = 0; m < 2; m++)
        #pragma unroll
        for (int n = 0; n < 8; n++)
            #pragma unroll
            for (int i = 0; i < 4; i++) acc[m][n][i] = 0.0f;

    #define LOAD_STAGE_Q(st, it)                                                \
    do {                                                                         \
        const int j0 = (it) * 64;                                               \
        const uint32_t sah = sbase + (st) * QSTAGE_B;                           \
        const uint32_t sal = sah + QA_B;                                        \
        const uint32_t sbh = sal + QA_B;                                        \
        const uint32_t sbl = sbh + QB_B;                                        \
        _Pragma("unroll")                                                       \
        for (int u = 0; u < 4; u++) {                                           \
            int c = tid + u * 256;                                              \
            int r  = c >> 3;                                                    \
            int k8 = (c & 7) * 8;                                               \
            uint32_t off = (uint32_t)(r * QLDA + k8) * 2;                       \
            cp16(sah + off, g_xh + (size_t)(row0 + r) * DD + j0 + k8);          \
            cp16(sal + off, g_xl + (size_t)(row0 + r) * DD + j0 + k8);          \
        }                                                                       \
        _Pragma("unroll")                                                       \
        for (int u = 0; u < 4; u++) {                                           \
            int c = tid + u * 256;                                              \
            int r  = c >> 4;                                                    \
            int n8 = (c & 15) * 8;                                              \
            uint32_t off = (uint32_t)(r * QLDB + n8) * 2;                       \
            cp16(sbh + off, Wh + (size_t)(j0 + r) * DD + n0 + n8);              \
            cp16(sbl + off, Wl + (size_t)(j0 + r) * DD + n0 + n8);              \
        }                                                                       \
    } while (0)

    LOAD_STAGE_Q(0, 0); cp_commit();
    LOAD_STAGE_Q(1, 1); cp_commit();

    int buf = 0;
    for (int it = 0; it < Q_ITERS; ++it) {
        cp_wait<1>();
        __syncthreads();
        const uint32_t sah = sbase + buf * QSTAGE_B;
        const uint32_t sal = sah + QA_B;
        const uint32_t sbh = sal + QA_B;
        const uint32_t sbl = sbh + QB_B;

        #pragma unroll
        for (int kk = 0; kk < 4; kk++) {
            uint32_t ah[2][4], al[2][4];
            #pragma unroll
            for (int mf = 0; mf < 2; mf++) {
                int arow = warp_m * 32 + mf * 16 + (lane & 15);
                int acol = kk * 16 + (lane >> 4) * 8;
                uint32_t off = (uint32_t)(arow * QLDA + acol) * 2;
                ldm_x4(sah + off, ah[mf][0], ah[mf][1], ah[mf][2], ah[mf][3]);
                ldm_x4(sal + off, al[mf][0], al[mf][1], al[mf][2], al[mf][3]);
            }
            uint32_t b[8][2];
            #pragma unroll
            for (int nq = 0; nq < 4; nq++) {
                int brow = kk * 16 + (lane & 15);
                int bcol = warp_n * 64 + nq * 16 + (lane >> 4) * 8;
                uint32_t off = (uint32_t)(brow * QLDB + bcol) * 2;
                ldm_x4_t(sbh + off, b[nq*2][0], b[nq*2][1], b[nq*2+1][0], b[nq*2+1][1]);
            }
            #pragma unroll
            for (int mf = 0; mf < 2; mf++)
                #pragma unroll
                for (int nf = 0; nf < 8; nf++) {
                    mma16816(acc[mf][nf], ah[mf], b[nf][0], b[nf][1]);
                    mma16816(acc[mf][nf], al[mf], b[nf][0], b[nf][1]);
                }
            #pragma unroll
            for (int nq = 0; nq < 4; nq++) {
                int brow = kk * 16 + (lane & 15);
                int bcol = warp_n * 64 + nq * 16 + (lane >> 4) * 8;
                uint32_t off = (uint32_t)(brow * QLDB + bcol) * 2;
                ldm_x4_t(sbl + off, b[nq*2][0], b[nq*2][1], b[nq*2+1][0], b[nq*2+1][1]);
            }
            #pragma unroll
            for (int mf = 0; mf < 2; mf++)
                #pragma unroll
                for (int nf = 0; nf < 8; nf++)
                    mma16816(acc[mf][nf], ah[mf], b[nf][0], b[nf][1]);
        }
        __syncthreads();
        if (it + QNSTAGE < Q_ITERS) LOAD_STAGE_Q(buf, it + QNSTAGE);
        cp_commit();
        if (++buf == QNSTAGE) buf = 0;
    }

    // epilogue: +bias; z==1 -> split to g_kh/g_kl, else fp32 to g_q/g_v
    const float* bias = (z == 0) ? bq : (z == 1) ? bk : bv;
    #pragma unroll
    for (int mf = 0; mf < 2; mf++) {
        #pragma unroll
        for (int rr = 0; rr < 2; rr++) {
            int row = row0 + warp_m * 32 + mf * 16 + rr * 8 + (lane >> 2);
            #pragma unroll
            for (int nf = 0; nf < 8; nf++) {
                int col = n0 + warp_n * 64 + nf * 8 + (lane & 3) * 2;
                float v0 = acc[mf][nf][rr * 2 + 0] + bias[col];
                float v1 = acc[mf][nf][rr * 2 + 1] + bias[col + 1];
                size_t o = (size_t)row * DD + col;
                if (z == 0) {
                    *(float2*)(g_q + o) = make_float2(v0, v1);
                } else if (z == 2) {
                    *(float2*)(g_v + o) = make_float2(v0, v1);
                } else {
                    __half h0 = __float2half_rn(v0);
                    __half h1 = __float2half_rn(v1);
                    __half l0 = __float2half_rn(v0 - __half2float(h0));
                    __half l1 = __float2half_rn(v1 - __half2float(h1));
                    *(__half2*)(g_kh + o) = __halves2half2(h0, h1);
                    *(__half2*)(g_kl + o) = __halves2half2(l0, l1);
                }
            }
        }
    }
}

// ---------------------------------------------------------------------------
// Kernel: s partials via fp16 mma.sync. Grid (64 Mtiles, 2 Ntiles, 2 Khalves),
// 256 threads, 2 CTAs/SM (2 stages, regs capped at 128). KC=64, 64 iters.
// ---------------------------------------------------------------------------
#define S_ITERS   (NN / 2 / 64)             // 64
#define SLDA      72
#define SLDB      136
#define SA_B      (128 * SLDA * 2)          // 18432
#define SB_B      (64 * SLDB * 2)           // 17408
#define SSTAGE_B  (SA_B + 2 * SB_B)         // 53248
#define SNSTAGE   2

__global__ __launch_bounds__(256, 2) void smma_kernel()
{
    extern __shared__ char smem[];
    __shared__ float srow[2][128];

    const int tid  = threadIdx.x;
    const int wid  = tid >> 5;
    const int lane = tid & 31;
    const int warp_m = wid >> 1;
    const int warp_n = wid & 1;
    const int row0 = blockIdx.x * 128;
    const int n0   = blockIdx.y * 128;
    const int kbase = blockIdx.z * (NN / 2);
    const uint32_t sbase = cvta_smem(smem);

    float acc[2][8][4];
    #pragma unroll
    for (int m = 0; m < 2; m++)
        #pragma unroll
        for (int n = 0; n < 8; n++)
            #pragma unroll
            for (int i = 0; i < 4; i++) acc[m][n][i] = 0.0f;

    #define LOAD_STAGE_S(st, it)                                                \
    do {                                                                         \
        const int j0 = kbase + (it) * 64;                                       \
        const uint32_t sa = sbase + (st) * SSTAGE_B;                            \
        const uint32_t sh = sa + SA_B;                                          \
        const uint32_t sl = sh + SB_B;                                          \
        _Pragma("unroll")                                                       \
        for (int u = 0; u < 4; u++) {                                           \
            int c = tid + u * 256;                                              \
            int r  = c >> 3;                                                    \
            int k8 = (c & 7) * 8;                                               \
            cp16(sa + (uint32_t)(r * SLDA + k8) * 2,                            \
                 g_adj_h + (size_t)(row0 + r) * NN + j0 + k8);                  \
        }                                                                       \
        _Pragma("unroll")                                                       \
        for (int u = 0; u < 4; u++) {                                           \
            int c = tid + u * 256;                                              \
            int r  = c >> 4;                                                    \
            int n8 = (c & 15) * 8;                                              \
            uint32_t off = (uint32_t)(r * SLDB + n8) * 2;                       \
            cp16(sh + off, g_kh + (size_t)(j0 + r) * DD + n0 + n8);             \
            cp16(sl + off, g_kl + (size_t)(j0 + r) * DD + n0 + n8);             \
        }                                                                       \
    } while (0)

    LOAD_STAGE_S(0, 0); cp_commit();
    LOAD_STAGE_S(1, 1); cp_commit();

    int buf = 0;
    for (int it = 0; it < S_ITERS; ++it) {
        cp_wait<1>();
        __syncthreads();
        const uint32_t sa = sbase + buf * SSTAGE_B;
        const uint32_t sh = sa + SA_B;
        const uint32_t sl = sh + SB_B;

        #pragma unroll
        for (int kk = 0; kk < 4; kk++) {
            uint32_t a[2][4];
            #pragma unroll
            for (int mf = 0; mf < 2; mf++) {
                int arow = warp_m * 32 + mf * 16 + (lane & 15);
                int acol = kk * 16 + (lane >> 4) * 8;
                ldm_x4(sa + (uint32_t)(arow * SLDA + acol) * 2,
                       a[mf][0], a[mf][1], a[mf][2], a[mf][3]);
            }
            uint32_t b[8][2];
            #pragma unroll
            for (int nq = 0; nq < 4; nq++) {
                int brow = kk * 16 + (lane & 15);
                int bcol = warp_n * 64 + nq * 16 + (lane >> 4) * 8;
                uint32_t off = (uint32_t)(brow * SLDB + bcol) * 2;
                ldm_x4_t(sh + off, b[nq*2][0], b[nq*2][1], b[nq*2+1][0], b[nq*2+1][1]);
            }
            #pragma unroll
            for (int mf = 0; mf < 2; mf++)
                #pragma unroll
                for (int nf = 0; nf < 8; nf++)
                    mma16816(acc[mf][nf], a[mf], b[nf][0], b[nf][1]);
            #pragma unroll
            for (int nq = 0; nq < 4; nq++) {
                int brow = kk * 16 + (lane & 15);
                int bcol = warp_n * 64 + nq * 16 + (lane >> 4) * 8;
                uint32_t off = (uint32_t)(brow * SLDB + bcol) * 2;
                ldm_x4_t(sl + off, b[nq*2][0], b[nq*2][1], b[nq*2+1][0], b[nq*2+1][1]);
            }
            #pragma unroll
            for (int mf = 0; mf < 2; mf++)
                #pragma unroll
                for (int nf = 0; nf < 8; nf++)
                    mma16816(acc[mf][nf], a[mf], b[nf][0], b[nf][1]);
        }
        __syncthreads();
        if (it + SNSTAGE < S_ITERS) LOAD_STAGE_S(buf, it + SNSTAGE);
        cp_commit();
        if (++buf == SNSTAGE) buf = 0;
    }

    // fused epilogue: p[row] = sum_n m[row][n] * q[row][n0+n]
    #pragma unroll
    for (int mf = 0; mf < 2; mf++) {
        #pragma unroll
        for (int rr = 0; rr < 2; rr++) {
            int lrow = warp_m * 32 + mf * 16 + rr * 8 + (lane >> 2);
            int grow = row0 + lrow;
            float p = 0.0f;
            #pragma unroll
            for (int nf = 0; nf < 8; nf++) {
                int gcol = n0 + warp_n * 64 + nf * 8 + (lane & 3) * 2;
                float2 qq = *(const float2*)(g_q + (size_t)grow * DD + gcol);
                p += acc[mf][nf][rr * 2 + 0] * qq.x
                   + acc[mf][nf][rr * 2 + 1] * qq.y;
            }
            p += __shfl_xor_sync(0xffffffffu, p, 1);
            p += __shfl_xor_sync(0xffffffffu, p, 2);
            if ((lane & 3) == 0) srow[warp_n][lrow] = p;
        }
    }
    __syncthreads();
    if (tid < 128)
        g_spart[(size_t)(blockIdx.y * 2 + blockIdx.z) * NN + row0 + tid] =
            srow[0][tid] + srow[1][tid];
}

// ---------------------------------------------------------------------------
// softmax over s = sum of 4 partials
// ---------------------------------------------------------------------------
__global__ __launch_bounds__(1024) void softmax_kernel(float* __restrict__ alpha_out,
                                                       int write_tail)
{
    __shared__ float red[32];
    const int tid = threadIdx.x;
    const int lane = tid & 31;
    const int wid = tid >> 5;

    float lmax = -3.4e38f;
    for (int i = tid; i < NN; i += 1024) {
        float sv = g_spart[i] + g_spart[NN + i] + g_spart[2 * NN + i] + g_spart[3 * NN + i];
        g_s[i] = sv;
        lmax = fmaxf(lmax, sv);
    }
    #pragma unroll
    for (int off = 16; off > 0; off >>= 1)
        lmax = fmaxf(lmax, __shfl_xor_sync(0xffffffffu, lmax, off));
    if (lane == 0) red[wid] = lmax;
    __syncthreads();
    float m = red[lane];
    #pragma unroll
    for (int off = 16; off > 0; off >>= 1)
        m = fmaxf(m, __shfl_xor_sync(0xffffffffu, m, off));
    __syncthreads();

    float lsum = 0.0f;
    for (int i = tid; i < NN; i += 1024) {
        float e = expf(g_s[i] - m);
        g_alpha[i] = e;
        lsum += e;
    }
    #pragma unroll
    for (int off = 16; off > 0; off >>= 1)
        lsum += __shfl_xor_sync(0xffffffffu, lsum, off);
    if (lane == 0) red[wid] = lsum;
    __syncthreads();
    float ssum = red[lane];
    #pragma unroll
    for (int off = 16; off > 0; off >>= 1)
        ssum += __shfl_xor_sync(0xffffffffu, ssum, off);
    float inv = 1.0f / ssum;

    for (int i = tid; i < NN; i += 1024) {
        float a = g_alpha[i] * inv;
        g_alpha[i] = a;
        if (write_tail) alpha_out[i] = a;
    }
}

// ---------------------------------------------------------------------------
// out[i, :] = alpha[i] * v[i, :]
// ---------------------------------------------------------------------------
__global__ __launch_bounds__(256) void out_kernel(float* __restrict__ out)
{
    int idx = blockIdx.x * blockDim.x + threadIdx.x;
    const int total4 = NN * DD / 4;
    if (idx >= total4) return;
    int row = (idx * 4) / DD;
    float a = g_alpha[row];
    float4 v4 = *(const float4*)(g_v + (size_t)idx * 4);
    v4.x *= a; v4.y *= a; v4.z *= a; v4.w *= a;
    *(float4*)(out + (size_t)idx * 4) = v4;
}

// ---------------------------------------------------------------------------
extern "C" void kernel_launch(void* const* d_in, const int* in_sizes, int n_in,
                              void* d_out, int out_size) {
    const float* x   = (const float*)d_in[0];
    const float* adj = (const float*)d_in[1];
    const float* Wq  = (const float*)d_in[2];
    const float* bq  = (const float*)d_in[3];
    const float* Wk  = (const float*)d_in[4];
    const float* bk  = (const float*)d_in[5];
    const float* Wv  = (const float*)d_in[6];
    const float* bv  = (const float*)d_in[7];
    float* out = (float*)d_out;

    // adj -> fp16 (largest independent convert; issue first)
    {
        size_t total4 = (size_t)NN * NN / 4;
        adj2h_kernel<<<(unsigned)((total4 + 255) / 256), 256>>>(adj);
    }
    // x, W -> fp16 hi/lo
    {
        size_t total4 = (size_t)NN * DD / 4;
        xsplit_kernel<<<(unsigned)((total4 + 255) / 256), 256>>>(x);
        wsplit_kernel<<<(3 * DD * DD + 255) / 256, 256>>>(Wq, Wk, Wv);
    }

    // q/k/v projections via mma (k written directly as hi/lo splits)
    cudaFuncSetAttribute(qkvmma_kernel, cudaFuncAttributeMaxDynamicSharedMemorySize,
                         QNSTAGE * QSTAGE_B);
    dim3 gq(NN / 128, 2, 3);
    qkvmma_kernel<<<gq, 256, QNSTAGE * QSTAGE_B>>>(bq, bk, bv);

    // s partials via fp16 mma GEMM + fused rowdot epilogue
    cudaFuncSetAttribute(smma_kernel, cudaFuncAttributeMaxDynamicSharedMemorySize,
                         SNSTAGE * SSTAGE_B);
    dim3 gs(NN / 128, 2, 2);
    smma_kernel<<<gs, 256, SNSTAGE * SSTAGE_B>>>();

    // softmax
    int write_tail = (out_size >= NN * DD + NN) ? 1 : 0;
    softmax_kernel<<<1, 1024>>>(out + (size_t)NN * DD, write_tail);

    // out = alpha[:,None] * v
    int total4 = NN * DD / 4;
    out_kernel<<<(total4 + 255) / 256, 256>>>(out);
}